// round 2
// baseline (speedup 1.0000x reference)
#include <cuda_runtime.h>
#include <math.h>

// ---------------- static scratch (no allocation allowed) ----------------
#define N_MAX 150016
#define E_MAX 900032
#define C_MAX 256

__device__ float g_x[(size_t)N_MAX * 256];   // activations (stride = layer dim)
__device__ float g_y[(size_t)N_MAX * 256];   // pre-BN / fc0 output
__device__ float g_z[(size_t)N_MAX * 96];    // aggregated input features
__device__ int   g_deg[N_MAX];
__device__ int   g_cursor[N_MAX];
__device__ int   g_rowptr[N_MAX + 1];
__device__ int   g_csr_src[E_MAX];
__device__ float g_csr_w[E_MAX];
__device__ float g_dinv[N_MAX];
__device__ float g_cs[N_MAX];
__device__ int   g_blocksum[256];
__device__ int   g_blockoff[256];
__device__ float g_sum[C_MAX];
__device__ float g_sq[C_MAX];
__device__ float g_scale[C_MAX];
__device__ float g_shift[C_MAX];
__device__ float g_pool[64 * 128];
__device__ int   g_starts[65];

// ---------------- small utility kernels ----------------
__global__ void k_zero_degcur(int n) {
    int i = blockIdx.x * blockDim.x + threadIdx.x;
    if (i < n) { g_deg[i] = 0; g_cursor[i] = 0; }
}

__global__ void k_zero_stats() {
    int i = threadIdx.x;
    if (i < C_MAX) { g_sum[i] = 0.f; g_sq[i] = 0.f; }
}

__global__ void k_hist(const int* __restrict__ dst, int e) {
    int i = blockIdx.x * blockDim.x + threadIdx.x;
    if (i < e) atomicAdd(&g_deg[dst[i]], 1);
}

__global__ void k_dinv(int n) {
    int i = blockIdx.x * blockDim.x + threadIdx.x;
    if (i < n) {
        float d = (float)(g_deg[i] + 1);
        float r = rsqrtf(d);
        g_dinv[i] = r;
        g_cs[i] = r * r;
    }
}

// exclusive scan of g_deg -> g_rowptr  (3 stages)
__global__ void k_scan1(int n) {
    __shared__ int sh[1024];
    int t = threadIdx.x;
    int idx = blockIdx.x * 1024 + t;
    int v = (idx < n) ? g_deg[idx] : 0;
    sh[t] = v;
    __syncthreads();
    for (int off = 1; off < 1024; off <<= 1) {
        int add = (t >= off) ? sh[t - off] : 0;
        __syncthreads();
        sh[t] += add;
        __syncthreads();
    }
    if (idx < n) g_rowptr[idx] = sh[t] - v;      // exclusive
    if (t == 1023) g_blocksum[blockIdx.x] = sh[t];
}

__global__ void k_scan2(int nb, int n) {
    if (threadIdx.x == 0) {
        int run = 0;
        for (int i = 0; i < nb; i++) { g_blockoff[i] = run; run += g_blocksum[i]; }
        g_rowptr[n] = run;   // == E
    }
}

__global__ void k_scan3(int n) {
    int idx = blockIdx.x * 1024 + threadIdx.x;
    if (idx < n) g_rowptr[idx] += g_blockoff[idx >> 10];
}

__global__ void k_place(const int* __restrict__ src, const int* __restrict__ dst, int e) {
    int i = blockIdx.x * blockDim.x + threadIdx.x;
    if (i < e) {
        int d = dst[i], s = src[i];
        int p = g_rowptr[d] + atomicAdd(&g_cursor[d], 1);
        g_csr_src[p] = s;
        g_csr_w[p] = g_dinv[s] * g_dinv[d];
    }
}

// ---------------- aggregation: g_z = sum_in x[src]*ce + x*cs (warp per node) ----
// use_ext != 0 -> input is xext (pos, din=3); otherwise input is g_x.
__global__ void k_agg(const float* __restrict__ xext, int use_ext, int n, int din) {
    const float* __restrict__ x = use_ext ? xext : g_x;
    int gt = blockIdx.x * blockDim.x + threadIdx.x;
    int node = gt >> 5;
    int lane = gt & 31;
    if (node >= n) return;
    int beg = g_rowptr[node], end = g_rowptr[node + 1];
    int c0 = lane, c1 = lane + 32, c2 = lane + 64;
    float a0 = 0.f, a1 = 0.f, a2 = 0.f;
    for (int ePos = beg; ePos < end; ePos++) {
        int s = g_csr_src[ePos];
        float w = g_csr_w[ePos];
        const float* xs = x + (size_t)s * din;
        if (c0 < din) a0 += xs[c0] * w;
        if (c1 < din) a1 += xs[c1] * w;
        if (c2 < din) a2 += xs[c2] * w;
    }
    float cw = g_cs[node];
    const float* xi = x + (size_t)node * din;
    float* zi = g_z + (size_t)node * din;
    if (c0 < din) zi[c0] = a0 + xi[c0] * cw;
    if (c1 < din) zi[c1] = a1 + xi[c1] * cw;
    if (c2 < din) zi[c2] = a2 + xi[c2] * cw;
}

// ---------------- SGEMM: g_y = A(MxK) * B(KxN) + bias, optional relu --------
// asel == 0 -> A = g_z (aggregated features); asel == 1 -> A = g_x.
#define BM 128
#define BN 64
#define BK 16
__global__ __launch_bounds__(256) void k_gemm(
    int asel, const float* __restrict__ Bm,
    const float* __restrict__ bias,
    int M, int K, int Nc, int relu)
{
    const float* __restrict__ A = asel ? g_x : g_z;
    float* __restrict__ C = g_y;
    __shared__ float As[BK][BM + 4];
    __shared__ float Bs[BK][BN];
    int tid = threadIdx.x;
    int tx = tid & 15;      // 0..15 -> cols
    int ty = tid >> 4;      // 0..15 -> rows
    int row0 = blockIdx.y * BM;
    int col0 = blockIdx.x * BN;

    float acc[8][4];
    #pragma unroll
    for (int i = 0; i < 8; i++)
        #pragma unroll
        for (int j = 0; j < 4; j++) acc[i][j] = 0.f;

    for (int k0 = 0; k0 < K; k0 += BK) {
        // load A tile: 128 rows x 16 k
        #pragma unroll
        for (int j = 0; j < 8; j++) {
            int r = (tid >> 4) + j * 16;
            int gk = k0 + (tid & 15);
            float v = 0.f;
            if (row0 + r < M && gk < K) v = A[(size_t)(row0 + r) * K + gk];
            As[tid & 15][r] = v;
        }
        // load B tile: 16 k x 64 n
        #pragma unroll
        for (int j = 0; j < 4; j++) {
            int kk = (tid >> 6) + j * 4;
            int nn = tid & 63;
            float v = 0.f;
            int gk = k0 + kk;
            if (gk < K && col0 + nn < Nc) v = Bm[(size_t)gk * Nc + col0 + nn];
            Bs[kk][nn] = v;
        }
        __syncthreads();
        #pragma unroll
        for (int k = 0; k < BK; k++) {
            float af[8], bf[4];
            #pragma unroll
            for (int i = 0; i < 8; i++) af[i] = As[k][ty * 8 + i];
            #pragma unroll
            for (int j = 0; j < 4; j++) bf[j] = Bs[k][tx * 4 + j];
            #pragma unroll
            for (int i = 0; i < 8; i++)
                #pragma unroll
                for (int j = 0; j < 4; j++)
                    acc[i][j] = fmaf(af[i], bf[j], acc[i][j]);
        }
        __syncthreads();
    }
    #pragma unroll
    for (int i = 0; i < 8; i++) {
        int r = row0 + ty * 8 + i;
        if (r >= M) continue;
        #pragma unroll
        for (int j = 0; j < 4; j++) {
            int c = col0 + tx * 4 + j;
            if (c >= Nc) continue;
            float v = acc[i][j] + bias[c];
            if (relu) v = fmaxf(v, 0.f);
            C[(size_t)r * Nc + c] = v;
        }
    }
}

// ---------------- BN stats: per-channel sum / sumsq over g_y ----------------
__global__ void k_stats(int M, int Nc) {
    __shared__ float ssum[512];
    __shared__ float ssq[512];
    int c = threadIdx.x, yy = threadIdx.y, by = blockDim.y;
    float s = 0.f, q = 0.f;
    for (int r = blockIdx.x * by + yy; r < M; r += gridDim.x * by) {
        float v = g_y[(size_t)r * Nc + c];
        s += v; q += v * v;
    }
    ssum[yy * Nc + c] = s;
    ssq[yy * Nc + c] = q;
    __syncthreads();
    if (yy == 0) {
        for (int j = 1; j < by; j++) { s += ssum[j * Nc + c]; q += ssq[j * Nc + c]; }
        atomicAdd(&g_sum[c], s);
        atomicAdd(&g_sq[c], q);
    }
}

__global__ void k_finalize(const float* __restrict__ gamma, const float* __restrict__ beta,
                           int M, int Nc) {
    int c = threadIdx.x;
    if (c < Nc) {
        float inv = 1.f / (float)M;
        float mean = g_sum[c] * inv;
        float var = g_sq[c] * inv - mean * mean;
        float r = rsqrtf(var + 1e-5f);
        float a = gamma[c] * r;
        g_scale[c] = a;
        g_shift[c] = beta[c] - mean * a;
    }
}

__global__ void k_bnrelu(int M, int Nc) {
    int c = threadIdx.x, yy = threadIdx.y, by = blockDim.y;
    float a = g_scale[c], b = g_shift[c];
    for (int r = blockIdx.x * by + yy; r < M; r += gridDim.x * by) {
        size_t i = (size_t)r * Nc + c;
        g_x[i] = fmaxf(fmaf(g_y[i], a, b), 0.f);
    }
}

// ---------------- pooling & head ----------------
__global__ void k_bounds(const int* __restrict__ batch, int n, int nb) {
    int g = threadIdx.x;
    if (g > nb) return;
    int lo = 0, hi = n;
    while (lo < hi) {
        int mid = (lo + hi) >> 1;
        if (batch[mid] < g) lo = mid + 1; else hi = mid;
    }
    g_starts[g] = lo;
}

__global__ void k_segmax() {  // reads g_y (ld = 128)
    __shared__ float sh[4][128];
    int g = blockIdx.x, c = threadIdx.x, s = threadIdx.y;
    int beg = g_starts[g], end = g_starts[g + 1];
    float m = -3.4e38f;
    for (int r = beg + s; r < end; r += 4)
        m = fmaxf(m, g_y[(size_t)r * 128 + c]);
    sh[s][c] = m;
    __syncthreads();
    if (s == 0) {
        m = fmaxf(fmaxf(sh[0][c], sh[1][c]), fmaxf(sh[2][c], sh[3][c]));
        g_pool[g * 128 + c] = m;
    }
}

__global__ void k_head(const float* __restrict__ W1, const float* __restrict__ b1,
                       const float* __restrict__ W2, const float* __restrict__ b2,
                       const float* __restrict__ W3, const float* __restrict__ b3,
                       float* __restrict__ out) {
    __shared__ float xs[128];
    __shared__ float red[128];
    int g = blockIdx.x, c = threadIdx.x;
    xs[c] = g_pool[g * 128 + c];
    __syncthreads();

    float v = b1[c];
    #pragma unroll 8
    for (int k = 0; k < 128; k++) v = fmaf(xs[k], W1[k * 128 + c], v);
    v = fmaxf(v, 0.f);
    __syncthreads(); xs[c] = v; __syncthreads();

    v = b2[c];
    #pragma unroll 8
    for (int k = 0; k < 128; k++) v = fmaf(xs[k], W2[k * 128 + c], v);
    v = fmaxf(v, 0.f);
    __syncthreads(); xs[c] = v; __syncthreads();

    float v3 = b3[c];
    #pragma unroll 8
    for (int k = 0; k < 128; k++) v3 = fmaf(xs[k], W3[k * 128 + c], v3);

    red[c] = v3 * v3;
    __syncthreads();
    for (int off = 64; off > 0; off >>= 1) {
        if (c < off) red[c] += red[c + off];
        __syncthreads();
    }
    float nrm = fmaxf(sqrtf(red[0]), 1e-12f);
    out[g * 128 + c] = v3 / nrm;
}

// ---------------- host launch: kernel launches ONLY ----------------
extern "C" void kernel_launch(void* const* d_in, const int* in_sizes, int n_in,
                              void* d_out, int out_size) {
    const float* pos = (const float*)d_in[0];
    const int* ei = (const int*)d_in[1];
    const int* batch = (const int*)d_in[2];
    int n = in_sizes[0] / 3;
    int e = in_sizes[1] / 2;
    const int* src = ei;
    const int* dst = ei + e;
    float* out = (float*)d_out;

    const float *W[5], *bb[5], *gg[5], *be[5];
    for (int l = 0; l < 5; l++) {
        W[l] = (const float*)d_in[3 + 4 * l];
        bb[l] = (const float*)d_in[4 + 4 * l];
        gg[l] = (const float*)d_in[5 + 4 * l];
        be[l] = (const float*)d_in[6 + 4 * l];
    }
    const float* fc0_W = (const float*)d_in[23];
    const float* fc0_b = (const float*)d_in[24];
    const float* fc1_W = (const float*)d_in[25];
    const float* fc1_b = (const float*)d_in[26];
    const float* fc2_W = (const float*)d_in[27];
    const float* fc2_b = (const float*)d_in[28];
    const float* fc3_W = (const float*)d_in[29];
    const float* fc3_b = (const float*)d_in[30];

    // ---- graph preprocessing: degrees, CSR ----
    k_zero_degcur<<<(n + 255) / 256, 256>>>(n);
    k_hist<<<(e + 255) / 256, 256>>>(dst, e);
    k_dinv<<<(n + 255) / 256, 256>>>(n);
    int nb = (n + 1023) / 1024;
    k_scan1<<<nb, 1024>>>(n);
    k_scan2<<<1, 32>>>(nb, n);
    k_scan3<<<nb, 1024>>>(n);
    k_place<<<(e + 255) / 256, 256>>>(src, dst, e);

    // ---- 5 GCN layers ----
    int din[5] = {3, 16, 32, 64, 94};
    int dou[5] = {16, 32, 64, 94, 256};
    for (int l = 0; l < 5; l++) {
        int K = din[l], Nc = dou[l];
        k_agg<<<(n + 7) / 8, 256>>>(pos, l == 0 ? 1 : 0, n, K);
        dim3 gg_((Nc + BN - 1) / BN, (n + BM - 1) / BM);
        k_gemm<<<gg_, 256>>>(0, W[l], bb[l], n, K, Nc, 0);
        k_zero_stats<<<1, 256>>>();
        int by = 512 / Nc; if (by < 1) by = 1; if (by > 8) by = 8;
        dim3 bdim(Nc, by);
        k_stats<<<1024, bdim>>>(n, Nc);
        k_finalize<<<1, 256>>>(gg[l], be[l], n, Nc);
        k_bnrelu<<<1024, bdim>>>(n, Nc);
    }

    // ---- fc0 + relu (A = g_x, 256 -> 128) ----
    dim3 gfc((128 + BN - 1) / BN, (n + BM - 1) / BM);
    k_gemm<<<gfc, 256>>>(1, fc0_W, fc0_b, n, 256, 128, 1);

    // ---- segment max pool + head MLP + normalize ----
    k_bounds<<<1, 65>>>(batch, n, 64);
    k_segmax<<<64, dim3(128, 4)>>>();
    k_head<<<64, 128>>>(fc1_W, fc1_b, fc2_W, fc2_b, fc3_W, fc3_b, out);
}